// round 10
// baseline (speedup 1.0000x reference)
#include <cuda_runtime.h>
#include <stdint.h>

#define N_USERS 200000
#define N_ITEMS 100000
#define N_NODES 300000
#define N_EDGES 4800000
#define EMB 64
#define BATCH 4096
#define N_SEL 8192
#define CAP 128
#define NWORDS ((N_NODES + 31) / 32)

// Scratch (device globals; zero-initialized at module load)
__device__ unsigned           g_bits[NWORDS];     // batch membership bitmap
__device__ unsigned long long g_slotv[N_NODES];   // (gen<<13)|slot, gen-tagged
__device__ int                g_cnt[N_SEL];
__device__ uint2              g_list[N_SEL * CAP];
__device__ unsigned long long g_gen;              // completed-launch counter

// K1: claim slots with generation tags (no clearing needed) + zero counters.
// Winner among duplicate nodes = max slot id (deterministic).
__global__ void k_claim(const int* __restrict__ user_id,
                        const int* __restrict__ item_id) {
    int b = blockIdx.x * blockDim.x + threadIdx.x;
    if (b >= N_SEL) return;
    g_cnt[b] = 0;
    int node = (b < BATCH) ? user_id[b] : N_USERS + item_id[b - BATCH];
    unsigned long long tag = ((g_gen + 1ULL) << 13) | (unsigned long long)b;
    atomicOr(&g_bits[node >> 5], 1u << (node & 31));
    atomicMax(&g_slotv[node], tag);
}

// K2: coalesced edge scan, 8 edges/thread (2 independent int4 loads),
// L1-cached global bitmap filter, compact to per-slot lists.
__global__ void k_scan(const int*   __restrict__ adj_row,
                       const int*   __restrict__ adj_col,
                       const float* __restrict__ adj_vals) {
    int i = blockIdx.x * blockDim.x + threadIdx.x;   // 8 edges per thread
    if (i >= N_EDGES / 8) return;
    const int4* row4 = (const int4*)adj_row;
    int4 ra = row4[2 * i];
    int4 rb = row4[2 * i + 1];
    int e = i * 8;
    int rows[8] = {ra.x, ra.y, ra.z, ra.w, rb.x, rb.y, rb.z, rb.w};
#pragma unroll
    for (int k = 0; k < 8; k++) {
        int row = rows[k];
        unsigned w = g_bits[row >> 5];
        if ((w >> (row & 31)) & 1u) {
            // bit set => claimed THIS launch => tag is current
            int s = (int)(g_slotv[row] & 8191ULL);
            int pos = atomicAdd(&g_cnt[s], 1);
            if (pos < CAP)
                g_list[s * CAP + pos] =
                    make_uint2((unsigned)adj_col[e + k],
                               __float_as_uint(adj_vals[e + k]));
        }
    }
}

// K3: one warp per slot; uniform (broadcast) g_list loads — no shfl chain,
// no lane-staging loop. 4 independent edge groups for MLP. Winner
// indirection handles duplicates. Tail: clear bit, bump gen.
__global__ void k_acc(const int*   __restrict__ user_id,
                      const int*   __restrict__ item_id,
                      const float* __restrict__ user_emb,
                      const float* __restrict__ item_emb,
                      float*       __restrict__ out) {
    int s = blockIdx.x * (blockDim.x >> 5) + (threadIdx.x >> 5);
    int lane = threadIdx.x & 31;
    if (s >= N_SEL) return;

    int node = (s < BATCH) ? user_id[s] : N_USERS + item_id[s - BATCH];
    const float* xp = (node < N_USERS)
        ? user_emb + (size_t)node * EMB
        : item_emb + (size_t)(node - N_USERS) * EMB;
    float2 x2 = ((const float2*)xp)[lane];
    float ax = 2.0f * x2.x;
    float ay = 2.0f * x2.y;

    int w = (int)(g_slotv[node] & 8191ULL);   // winner slot for this node
    int n = g_cnt[w];
    if (n > CAP) n = CAP;
    const uint2* lst = g_list + (size_t)w * CAP;

    int k = 0;
    for (; k + 4 <= n; k += 4) {              // unpredicated 4-edge groups
        // uniform loads: every lane reads the same 8B -> broadcast, 1 sector
        uint2 e0 = lst[k + 0];
        uint2 e1 = lst[k + 1];
        uint2 e2 = lst[k + 2];
        uint2 e3 = lst[k + 3];
        const float2* p0 = ((int)e0.x < N_USERS)
            ? (const float2*)(user_emb + (size_t)e0.x * EMB)
            : (const float2*)(item_emb + (size_t)(e0.x - N_USERS) * EMB);
        const float2* p1 = ((int)e1.x < N_USERS)
            ? (const float2*)(user_emb + (size_t)e1.x * EMB)
            : (const float2*)(item_emb + (size_t)(e1.x - N_USERS) * EMB);
        const float2* p2 = ((int)e2.x < N_USERS)
            ? (const float2*)(user_emb + (size_t)e2.x * EMB)
            : (const float2*)(item_emb + (size_t)(e2.x - N_USERS) * EMB);
        const float2* p3 = ((int)e3.x < N_USERS)
            ? (const float2*)(user_emb + (size_t)e3.x * EMB)
            : (const float2*)(item_emb + (size_t)(e3.x - N_USERS) * EMB);
        float2 r0 = p0[lane];                 // 4 independent 256B loads
        float2 r1 = p1[lane];
        float2 r2 = p2[lane];
        float2 r3 = p3[lane];
        ax = fmaf(__uint_as_float(e0.y), r0.x, ax);
        ay = fmaf(__uint_as_float(e0.y), r0.y, ay);
        ax = fmaf(__uint_as_float(e1.y), r1.x, ax);
        ay = fmaf(__uint_as_float(e1.y), r1.y, ay);
        ax = fmaf(__uint_as_float(e2.y), r2.x, ax);
        ay = fmaf(__uint_as_float(e2.y), r2.y, ay);
        ax = fmaf(__uint_as_float(e3.y), r3.x, ax);
        ay = fmaf(__uint_as_float(e3.y), r3.y, ay);
    }
    for (; k < n; k++) {                      // scalar tail
        uint2 e = lst[k];
        const float2* p = ((int)e.x < N_USERS)
            ? (const float2*)(user_emb + (size_t)e.x * EMB)
            : (const float2*)(item_emb + (size_t)(e.x - N_USERS) * EMB);
        float2 r = p[lane];
        ax = fmaf(__uint_as_float(e.y), r.x, ax);
        ay = fmaf(__uint_as_float(e.y), r.y, ay);
    }
    ((float2*)out)[(size_t)s * 32 + lane] = make_float2(ax, ay);

    // cleanup for next replay: clear this node's bit (idempotent)
    if (lane == 0) {
        atomicAnd(&g_bits[node >> 5], ~(1u << (node & 31)));
        if (s == 0) atomicAdd(&g_gen, 1ULL);  // next launch uses gen+1
    }
}

extern "C" void kernel_launch(void* const* d_in, const int* in_sizes, int n_in,
                              void* d_out, int out_size) {
    const float* user_emb = (const float*)d_in[0];
    const float* item_emb = (const float*)d_in[1];
    const int*   adj_row  = (const int*)d_in[2];
    const int*   adj_col  = (const int*)d_in[3];
    const float* adj_vals = (const float*)d_in[4];
    const int*   user_id  = (const int*)d_in[5];
    const int*   item_id  = (const int*)d_in[6];
    float*       out      = (float*)d_out;

    k_claim<<<N_SEL / 128, 128>>>(user_id, item_id);
    k_scan <<<(N_EDGES / 8 + 255) / 256, 256>>>(adj_row, adj_col, adj_vals);
    k_acc  <<<N_SEL / 8, 256>>>(user_id, item_id, user_emb, item_emb, out);
}